// round 4
// baseline (speedup 1.0000x reference)
#include <cuda_runtime.h>
#include <cuda_bf16.h>

// IDWT 2D (inverse Haar), reference-exact layout.
// Input x: (B=8, 4*C=256, H=128, W=128) fp32 -> Output (8, 64, 256, 256) fp32.
//
// Mapping (from the reference's raw (H,W,2,2)->(2H,2W) reshape):
//   input (i, j) produces float4 at row = 2i + (j>=64), col = 4*(j mod 64)
//   butterfly = (ll+lh+hl+hh, ll+lh-hl-hh, ll-lh+hl-hh, ll-lh-hl+hh)
//
// One thread per input j: per-warp 4x dense 128B loads (LDG.32) and one
// fully dense 512B store (STG.128, lane stride 16B -> every 32B sector
// written whole by a single instruction). Streams never re-read -> use
// __ldcs / __stcs evict-first hints.

static constexpr int B  = 8;
static constexpr int C  = 64;
static constexpr int H  = 128;
static constexpr int W  = 128;

static constexpr unsigned BAND_STRIDE = (unsigned)C * H * W;      // 1,048,576
static constexpr unsigned X_N_STRIDE  = 4u * BAND_STRIDE;
static constexpr unsigned O_C_STRIDE  = 2u * H * 2u * W;          // 65,536
static constexpr unsigned O_N_STRIDE  = (unsigned)C * O_C_STRIDE; // 4,194,304

__global__ void __launch_bounds__(256) idwt2d_kernel(const float* __restrict__ x,
                                                     float* __restrict__ out)
{
    unsigned tid = blockIdx.x * blockDim.x + threadIdx.x;  // 0 .. 2^23-1

    unsigned j = tid & (W - 1);          // 0..127
    unsigned t1 = tid >> 7;
    unsigned i = t1 & (H - 1);           // 0..127
    unsigned t2 = t1 >> 7;
    unsigned c = t2 & (C - 1);           // 0..63
    unsigned n = t2 >> 6;                // 0..7

    unsigned xbase = n * X_N_STRIDE + c * (H * W) + i * W + j;

    float ll = __ldcs(x + xbase + 0 * BAND_STRIDE);
    float lh = __ldcs(x + xbase + 1 * BAND_STRIDE);
    float hl = __ldcs(x + xbase + 2 * BAND_STRIDE);
    float hh = __ldcs(x + xbase + 3 * BAND_STRIDE);

    float s  = ll + lh;   // row-sum part
    float d  = ll - lh;   // row-diff part
    float sb = hl + hh;
    float db = hl - hh;

    float4 q;
    q.x = s + sb;   // (a,b)=(0,0)
    q.y = s - sb;   // (0,1)
    q.z = d + db;   // (1,0)
    q.w = d - db;   // (1,1)

    unsigned row = 2 * i + (j >> 6);
    unsigned col = (j & 63) * 4;

    unsigned obase = n * O_N_STRIDE + c * O_C_STRIDE + row * (2 * W) + col;

    __stcs((float4*)(out + obase), q);
}

extern "C" void kernel_launch(void* const* d_in, const int* in_sizes, int n_in,
                              void* d_out, int out_size)
{
    const float* x = (const float*)d_in[0];
    float* out = (float*)d_out;

    const unsigned total = (unsigned)B * C * H * W;  // 8,388,608
    const int threads = 256;
    const int blocks = total / threads;              // 32,768

    idwt2d_kernel<<<blocks, threads>>>(x, out);
}